// round 13
// baseline (speedup 1.0000x reference)
#include <cuda_runtime.h>
#include <cuda_fp16.h>
#include <cstdint>

#define N_HEAD   32
#define HEAD_DIM 32
#define N_EMBD   1024
#define VOCAB    32000
#define NTOK     128
#define NROWS    4096            // NTOK * N_HEAD
#define TEMP_MIN 0.1f
#define LOG2E    1.4426950408889634f

#define VT       128             // vocab columns per tile
#define NTILES   250             // 32000 / 128
#define NSPLIT   18
#define MTILES   32              // 4096 / 128

// padded tile layouts (LDSM-conflict-free strides)
#define SKV_ROW   80             // 32 f16 (64B) + 16B pad
#define SKV_TILE  (VT * SKV_ROW)          // 10240 B
#define SHV_ROW   272            // 128 f16 (256B) + 16B pad
#define SHV_NROW  32             // 32 data rows
#define SHV_TILE  (SHV_NROW * SHV_ROW)    // 8704 B

// ---------------- global scratch ----------------------------------------------
__device__ __align__(256) char g_Skv[NTILES * SKV_TILE];   // [tile][v][ch] f16 padded
__device__ __align__(256) char g_Shv[NTILES * SHV_TILE];   // [tile][ch][v] f16 padded
__device__ __align__(256) __half g_Qh[NROWS * 32];         // pre-scaled by log2e/temp
__device__ __align__(256) uint32_t g_OpartH[NSPLIT * NROWS * 16];  // f16x2-packed partials
__device__ __align__(256) float g_Zpart[NSPLIT * NROWS];
__device__ int g_cnt1[MTILES];
__device__ int g_cnt2[MTILES];

// ---------------- helpers ------------------------------------------------------
__device__ __forceinline__ uint32_t smem_to_u32(const void* p) {
    uint32_t a;
    asm("{ .reg .u64 t; cvta.to.shared.u64 t, %1; cvt.u32.u64 %0, t; }" : "=r"(a) : "l"(p));
    return a;
}
#define CP_ASYNC16(dst_u32, src_ptr) \
    asm volatile("cp.async.cg.shared.global [%0], [%1], 16;" \
                 :: "r"(dst_u32), "l"(src_ptr) : "memory")
#define CP_COMMIT()  asm volatile("cp.async.commit_group;" ::: "memory")
#define CP_WAIT(n)   asm volatile("cp.async.wait_group %0;" :: "n"(n) : "memory")

#define LDSM4(r0, r1, r2, r3, addr) \
    asm volatile("ldmatrix.sync.aligned.m8n8.x4.shared.b16 {%0,%1,%2,%3}, [%4];" \
                 : "=r"(r0), "=r"(r1), "=r"(r2), "=r"(r3) : "r"(addr))

// pack two f32 into f16x2 (first arg -> LOW half), then exp2 both
__device__ __forceinline__ uint32_t cvt_f16x2(float lo, float hi) {
    uint32_t r;
    asm("cvt.rn.f16x2.f32 %0, %1, %2;" : "=r"(r) : "f"(hi), "f"(lo));
    return r;
}
__device__ __forceinline__ uint32_t ex2_f16x2(uint32_t x) {
    uint32_t r;
    asm("ex2.approx.f16x2 %0, %1;" : "=r"(r) : "r"(x));
    return r;
}
__device__ __forceinline__ uint32_t hadd2u(uint32_t a, uint32_t b) {
    uint32_t r;
    asm("add.f16x2 %0, %1, %2;" : "=r"(r) : "r"(a), "r"(b));
    return r;
}
// D = A(16x16 f16,row) @ B(16x8 f16,col) + C  (f32 accum)
__device__ __forceinline__ void mma16816h(float* d, const uint32_t* a, const uint32_t* b0,
                                          const uint32_t* b1, const float* c) {
    asm("mma.sync.aligned.m16n8k16.row.col.f32.f16.f16.f32 "
        "{%0,%1,%2,%3}, {%4,%5,%6,%7}, {%8,%9}, {%10,%11,%12,%13};"
        : "=f"(d[0]), "=f"(d[1]), "=f"(d[2]), "=f"(d[3])
        : "r"(a[0]), "r"(a[1]), "r"(a[2]), "r"(a[3]),
          "r"(*b0), "r"(*b1),
          "f"(c[0]), "f"(c[1]), "f"(c[2]), "f"(c[3]));
}

// ---------------- kernel 1: build f16 S tiles + zero tickets -------------------
__global__ void __launch_bounds__(256)
build_S_tiles(const float* __restrict__ vocab_emb) {
    __shared__ __half T[128][34];                // +2 pad
    const int t = threadIdx.x, vt = blockIdx.x;
    const int v0 = vt * VT;

    if (vt == 0 && t < MTILES) { g_cnt1[t] = 0; g_cnt2[t] = 0; }

#pragma unroll
    for (int k = 0; k < 16; k++) {
        int idx = k * 256 + t;                   // 0..4095
        int v = idx >> 5, h = idx & 31;
        const float4* p = (const float4*)(vocab_emb + (size_t)(v0 + v) * N_EMBD + h * HEAD_DIM);
        float s = 0.f;
#pragma unroll
        for (int i = 0; i < 8; i++) { float4 f = p[i]; s += (f.x + f.y) + (f.z + f.w); }
        T[v][h] = __float2half_rn(s);
    }
    __syncthreads();

    char* gk = g_Skv + (size_t)vt * SKV_TILE;
#pragma unroll
    for (int k = 0; k < 8; k++) {
        int idx = k * 256 + t;                   // v=idx>>4, c=idx&15
        int v = idx >> 4, c = idx & 15;
        uint32_t val = *(const uint32_t*)&T[v][2 * c];
        *(uint32_t*)(gk + v * SKV_ROW + c * 4) = val;
    }
    char* gh = g_Shv + (size_t)vt * SHV_TILE;
#pragma unroll
    for (int k = 0; k < 8; k++) {
        int idx = k * 256 + t;                   // h=idx>>6, c=idx&63
        int h = idx >> 6, c = idx & 63;
        uint16_t a = *(const uint16_t*)&T[2 * c][h];
        uint16_t b = *(const uint16_t*)&T[2 * c + 1][h];
        uint32_t val = ((uint32_t)b << 16) | (uint32_t)a;
        *(uint32_t*)(gh + h * SHV_ROW + c * 4) = val;
    }
}

// ---------------- kernel 2: Q = FFN(x) * log2e/temp -> f16 ---------------------
__global__ void __launch_bounds__(256)
qbuild_kernel(const float* __restrict__ x,
              const float* __restrict__ W, const float* __restrict__ b,
              const float* __restrict__ temps) {
    __shared__ float sW[32 * 33];
    __shared__ float sx[8][32];
    const int t = threadIdx.x;
    const int row0 = blockIdx.x * 8;
#pragma unroll
    for (int k = 0; k < 4; k++) {
        int i = k * 256 + t;
        sW[(i >> 5) * 33 + (i & 31)] = W[i];
    }
    const int rl = t >> 5, d = t & 31;
    const int row = row0 + rl;
    sx[rl][d] = x[(size_t)row * 32 + d];
    __syncthreads();

    float s = b[d];
    const float* wr = sW + d * 33;
#pragma unroll
    for (int h = 0; h < 32; h++) s = fmaf(sx[rl][h], wr[h], s);
    float s2 = LOG2E / fmaxf(temps[row & 31], TEMP_MIN);
    g_Qh[row * 32 + d] = __float2half_rn(s * s2);
}

// ---------------- flash kernel (templated): hot loop identical to R12 ----------
// MODE 0: last CTA per m-tile merges partials + gate -> writes g_Qh (Q2)
// MODE 1: last CTA per m-tile merges partials -> normalizes -> writes out
template <int MODE>
__global__ void __launch_bounds__(128, 4)
flash_kernel(const float* __restrict__ x,
             const float* __restrict__ W_ref, const float* __restrict__ b_ref,
             const float* __restrict__ W_gate, const float* __restrict__ b_gate,
             const float* __restrict__ temps,
             float* __restrict__ out) {
    __shared__ __align__(16) char skv[2][SKV_TILE];
    __shared__ __align__(16) char shv[2][SHV_TILE];
    __shared__ int sticket;

    const int tid = threadIdx.x, w = tid >> 5, lane = tid & 31;
    const int gid = lane >> 2, tig = lane & 3;
    const int lane7 = lane & 7, laneg = lane >> 3;
    const int m = blockIdx.x & (MTILES - 1), s = blockIdx.x >> 5;
    const int rw0 = m * 128 + w * 32;
    const int t0 = (s * NTILES) / NSPLIT, t1 = ((s + 1) * NTILES) / NSPLIT;
    const int nT = t1 - t0;

    const uint32_t skv_b[2] = { smem_to_u32(skv[0]), smem_to_u32(skv[1]) };
    const uint32_t shv_b[2] = { smem_to_u32(shv[0]), smem_to_u32(shv[1]) };

    // ldmatrix per-lane offsets
    const uint32_t aA_off = (uint32_t)(lane7 * SKV_ROW + laneg * 16);
    const uint32_t bB_off = (uint32_t)((((laneg >> 1) * 8) + lane7) * SHV_ROW + (laneg & 1) * 16);

    // ---- persistent Q fragments ----
    uint32_t qf[2][2][4];
#pragma unroll
    for (int f = 0; f < 2; f++)
#pragma unroll
    for (int ks = 0; ks < 2; ks++) {
        int c0 = ks * 16 + 2 * tig;
        int rb = rw0 + 16 * f;
        qf[f][ks][0] = *(const uint32_t*)&g_Qh[(size_t)(rb + gid)     * 32 + c0];
        qf[f][ks][1] = *(const uint32_t*)&g_Qh[(size_t)(rb + gid + 8) * 32 + c0];
        qf[f][ks][2] = *(const uint32_t*)&g_Qh[(size_t)(rb + gid)     * 32 + c0 + 8];
        qf[f][ks][3] = *(const uint32_t*)&g_Qh[(size_t)(rb + gid + 8) * 32 + c0 + 8];
    }

    float outacc[2][4][4];
#pragma unroll
    for (int f = 0; f < 2; f++)
#pragma unroll
    for (int n2 = 0; n2 < 4; n2++)
#pragma unroll
        for (int k = 0; k < 4; k++) outacc[f][n2][k] = 0.f;
    float zf[2][2] = {{0.f, 0.f}, {0.f, 0.f}};   // [f][rowgroup] f32 Z accumulators

    // ---- cp.async tile copy (128 threads): SKV 640 chunks, SHV 544 chunks ----
    auto issue_tile = [&](int stg, int vt) {
        const char* gk = g_Skv + (size_t)vt * SKV_TILE;
        const char* gh = g_Shv + (size_t)vt * SHV_TILE;
        uint32_t dk = skv_b[stg], dh = shv_b[stg];
#pragma unroll
        for (int c = 0; c < 5; c++)
            CP_ASYNC16(dk + c * 2048 + tid * 16, gk + c * 2048 + tid * 16);
#pragma unroll
        for (int c = 0; c < 4; c++)
            CP_ASYNC16(dh + c * 2048 + tid * 16, gh + c * 2048 + tid * 16);
        if (tid < 32) CP_ASYNC16(dh + 8192 + tid * 16, gh + 8192 + tid * 16);
        CP_COMMIT();
    };

    issue_tile(0, t0);

    for (int i = 0; i < nT; i++) {
        const int stg = i & 1;
        __syncthreads();
        if (i + 1 < nT) issue_tile((i + 1) & 1, t0 + i + 1);
        if (i + 1 < nT) { CP_WAIT(1); } else { CP_WAIT(0); }
        __syncthreads();

        const uint32_t kv = skv_b[stg] + aA_off;
        const uint32_t hvB = shv_b[stg] + bB_off;

        // per-tile f16x2 Z accumulators (16 adds max, values ~O(10) -> safe)
        uint32_t zt[2][2] = {{0u, 0u}, {0u, 0u}};

#pragma unroll 2
        for (int c0 = 0; c0 < VT; c0 += 16) {  // 16-vocab chunk
            uint32_t bA0[4], bA1[4], bb[8];
            LDSM4(bA0[0], bA0[1], bA0[2], bA0[3], kv + (uint32_t)(c0 * SKV_ROW));
            LDSM4(bA1[0], bA1[1], bA1[2], bA1[3], kv + (uint32_t)((c0 + 8) * SKV_ROW));
            LDSM4(bb[0], bb[1], bb[2], bb[3], hvB + (uint32_t)(c0 * 2));
            LDSM4(bb[4], bb[5], bb[6], bb[7], hvB + (uint32_t)(c0 * 2) + 4352u);

            uint32_t pa[2][4];
#pragma unroll
            for (int f = 0; f < 2; f++) {
                float d0[4] = {0.f, 0.f, 0.f, 0.f}, d1[4] = {0.f, 0.f, 0.f, 0.f};
                mma16816h(d0, qf[f][0], &bA0[0], &bA0[1], d0);
                mma16816h(d0, qf[f][1], &bA0[2], &bA0[3], d0);
                mma16816h(d1, qf[f][0], &bA1[0], &bA1[1], d1);
                mma16816h(d1, qf[f][1], &bA1[2], &bA1[3], d1);
                pa[f][0] = ex2_f16x2(cvt_f16x2(d0[0], d0[1]));
                pa[f][1] = ex2_f16x2(cvt_f16x2(d0[2], d0[3]));
                pa[f][2] = ex2_f16x2(cvt_f16x2(d1[0], d1[1]));
                pa[f][3] = ex2_f16x2(cvt_f16x2(d1[2], d1[3]));
                zt[f][0] = hadd2u(zt[f][0], hadd2u(pa[f][0], pa[f][2]));
                zt[f][1] = hadd2u(zt[f][1], hadd2u(pa[f][1], pa[f][3]));
            }

#pragma unroll
            for (int n2 = 0; n2 < 4; n2++) {
                mma16816h(outacc[0][n2], pa[0], &bb[2 * n2], &bb[2 * n2 + 1], outacc[0][n2]);
                mma16816h(outacc[1][n2], pa[1], &bb[2 * n2], &bb[2 * n2 + 1], outacc[1][n2]);
            }
        }

        // fold tile Z into f32
#pragma unroll
        for (int f = 0; f < 2; f++)
#pragma unroll
        for (int r = 0; r < 2; r++) {
            float2 v = __half22float2(*(__half2*)&zt[f][r]);
            zf[f][r] += v.x + v.y;
        }
    }

    // ---- epilogue: reduce Z over the 4 tig lanes, write f16x2 partials ----
#pragma unroll
    for (int f = 0; f < 2; f++)
#pragma unroll
    for (int r = 0; r < 2; r++) {
        zf[f][r] += __shfl_xor_sync(0xFFFFFFFFu, zf[f][r], 1);
        zf[f][r] += __shfl_xor_sync(0xFFFFFFFFu, zf[f][r], 2);
    }

#pragma unroll
    for (int f = 0; f < 2; f++) {
        const int r0g = rw0 + 16 * f + gid, r1g = r0g + 8;
        if (tig == 0) {
            g_Zpart[s * NROWS + r0g] = zf[f][0];
            g_Zpart[s * NROWS + r1g] = zf[f][1];
        }
#pragma unroll
        for (int n2 = 0; n2 < 4; n2++) {
            g_OpartH[((size_t)s * NROWS + r0g) * 16 + n2 * 4 + tig] =
                cvt_f16x2(outacc[f][n2][0], outacc[f][n2][1]);
            g_OpartH[((size_t)s * NROWS + r1g) * 16 + n2 * 4 + tig] =
                cvt_f16x2(outacc[f][n2][2], outacc[f][n2][3]);
        }
    }

    // ---- last-CTA inline merge (threadFenceReduction pattern) ----
    __threadfence();
    __syncthreads();
    if (tid == 0) {
        int* cnt = (MODE == 0) ? g_cnt1 : g_cnt2;
        sticket = atomicAdd(&cnt[m], 1);
    }
    __syncthreads();
    if (sticket != NSPLIT - 1) return;
    __threadfence();

    const int row = m * 128 + tid;               // 128 rows, one per thread

    float Z = 0.f;
#pragma unroll
    for (int s2 = 0; s2 < NSPLIT; s2++) Z += g_Zpart[s2 * NROWS + row];
    const float iz = 1.0f / Z;

    if (MODE == 1) {
        // final: normalize and write out
#pragma unroll
        for (int j = 0; j < 16; j++) {
            float ax = 0.f, ay = 0.f;
#pragma unroll
            for (int s2 = 0; s2 < NSPLIT; s2++) {
                uint32_t u = g_OpartH[((size_t)s2 * NROWS + row) * 16 + j];
                float2 v = __half22float2(*(__half2*)&u);
                ax += v.x; ay += v.y;
            }
            *(float2*)&out[(size_t)row * 32 + 2 * j] = make_float2(ax * iz, ay * iz);
        }
    } else {
        // merge + gate -> Q2 (pre-scaled f16)
        float* sWr = (float*)skv;                // reuse stage smem (tiles consumed)
        float* sWg = sWr + 32 * 33;
#pragma unroll
        for (int k = 0; k < 8; k++) {
            int i = k * 128 + tid;               // 0..1023
            int di = (i >> 5) * 33 + (i & 31);
            sWr[di] = W_ref[i];
            sWg[di] = W_gate[i];
        }
        __syncthreads();

        float xr[32];
        const float4* xp = (const float4*)(x + (size_t)row * 32);
#pragma unroll
        for (int i = 0; i < 8; i++) {
            float4 f4 = xp[i];
            xr[4*i] = f4.x; xr[4*i+1] = f4.y; xr[4*i+2] = f4.z; xr[4*i+3] = f4.w;
        }
        const float s2t = LOG2E / fmaxf(temps[row & 31], TEMP_MIN);

#pragma unroll
        for (int j = 0; j < 16; j++) {
            float ax = 0.f, ay = 0.f;
#pragma unroll
            for (int s2 = 0; s2 < NSPLIT; s2++) {
                uint32_t u = g_OpartH[((size_t)s2 * NROWS + row) * 16 + j];
                float2 v = __half22float2(*(__half2*)&u);
                ax += v.x; ay += v.y;
            }
            float vout2[2] = { ax * iz, ay * iz };
#pragma unroll
            for (int e = 0; e < 2; e++) {
                int d = 2 * j + e;
                float sr = b_ref[d], sg = b_gate[d];
                const float* wr = sWr + d * 33;
                const float* wg = sWg + d * 33;
#pragma unroll
                for (int h = 0; h < 32; h++) {
                    float xv = xr[h];
                    sr = fmaf(xv, wr[h], sr);
                    sg = fmaf(xv, wg[h], sg);
                }
                float refv = tanhf(sr);
                float g = 1.0f / (1.0f + __expf(-sg));
                float q2 = vout2[e] * (1.0f - g) + refv * g;
                g_Qh[row * 32 + d] = __float2half_rn(q2 * s2t);
            }
        }
    }
}

// ---------------- launch -------------------------------------------------------
extern "C" void kernel_launch(void* const* d_in, const int* in_sizes, int n_in,
                              void* d_out, int out_size) {
    const float* x         = (const float*)d_in[0];
    const float* vocab_emb = (const float*)d_in[1];
    const float* W_ffn     = (const float*)d_in[2];
    const float* b_ffn     = (const float*)d_in[3];
    const float* temps     = (const float*)d_in[4];
    const float* W_ref     = (const float*)d_in[5];
    const float* b_ref     = (const float*)d_in[6];
    const float* W_gate    = (const float*)d_in[7];
    const float* b_gate    = (const float*)d_in[8];
    float* out = (float*)d_out;

    build_S_tiles<<<NTILES, 256>>>(vocab_emb);
    qbuild_kernel<<<NROWS / 8, 256>>>(x, W_ffn, b_ffn, temps);
    flash_kernel<0><<<MTILES * NSPLIT, 128>>>(x, W_ref, b_ref, W_gate, b_gate, temps, out);
    flash_kernel<1><<<MTILES * NSPLIT, 128>>>(x, W_ref, b_ref, W_gate, b_gate, temps, out);
}

// round 14
// speedup vs baseline: 1.1601x; 1.1601x over previous
#include <cuda_runtime.h>
#include <cuda_fp16.h>
#include <cstdint>

#define N_HEAD   32
#define HEAD_DIM 32
#define N_EMBD   1024
#define VOCAB    32000
#define NTOK     128
#define NROWS    4096            // NTOK * N_HEAD
#define TEMP_MIN 0.1f
#define LOG2E    1.4426950408889634f

#define VT       128             // vocab columns per tile
#define NTILES   250             // 32000 / 128
#define NSPLIT   23              // 736 CTAs ~= 148 SMs * 5 resident CTAs
#define MTILES   32              // 4096 / 128

// padded tile layouts (LDSM-conflict-free strides)
#define SKV_ROW   80             // 32 f16 (64B) + 16B pad
#define SKV_TILE  (VT * SKV_ROW)          // 10240 B
#define SHV_ROW   272            // 128 f16 (256B) + 16B pad
#define SHV_NROW  32             // 32 data rows
#define SHV_TILE  (SHV_NROW * SHV_ROW)    // 8704 B

// ---------------- global scratch ----------------------------------------------
__device__ __align__(256) char g_Skv[NTILES * SKV_TILE];   // [tile][v][ch] f16 padded
__device__ __align__(256) char g_Shv[NTILES * SHV_TILE];   // [tile][ch][v] f16 padded
__device__ __align__(256) __half g_Qh[NROWS * 32];         // pre-scaled by log2e/temp
__device__ __align__(256) uint32_t g_OpartH[NSPLIT * NROWS * 16];  // f16x2-packed partials
__device__ __align__(256) float g_Zpart[NSPLIT * NROWS];

// ---------------- helpers ------------------------------------------------------
__device__ __forceinline__ uint32_t smem_to_u32(const void* p) {
    uint32_t a;
    asm("{ .reg .u64 t; cvta.to.shared.u64 t, %1; cvt.u32.u64 %0, t; }" : "=r"(a) : "l"(p));
    return a;
}
#define CP_ASYNC16(dst_u32, src_ptr) \
    asm volatile("cp.async.cg.shared.global [%0], [%1], 16;" \
                 :: "r"(dst_u32), "l"(src_ptr) : "memory")
#define CP_COMMIT()  asm volatile("cp.async.commit_group;" ::: "memory")
#define CP_WAIT(n)   asm volatile("cp.async.wait_group %0;" :: "n"(n) : "memory")

#define LDSM4(r0, r1, r2, r3, addr) \
    asm volatile("ldmatrix.sync.aligned.m8n8.x4.shared.b16 {%0,%1,%2,%3}, [%4];" \
                 : "=r"(r0), "=r"(r1), "=r"(r2), "=r"(r3) : "r"(addr))

// pack two f32 into f16x2 (first arg -> LOW half), then exp2 both
__device__ __forceinline__ uint32_t cvt_f16x2(float lo, float hi) {
    uint32_t r;
    asm("cvt.rn.f16x2.f32 %0, %1, %2;" : "=r"(r) : "f"(hi), "f"(lo));
    return r;
}
__device__ __forceinline__ uint32_t ex2_f16x2(uint32_t x) {
    uint32_t r;
    asm("ex2.approx.f16x2 %0, %1;" : "=r"(r) : "r"(x));
    return r;
}
__device__ __forceinline__ uint32_t hadd2u(uint32_t a, uint32_t b) {
    uint32_t r;
    asm("add.f16x2 %0, %1, %2;" : "=r"(r) : "r"(a), "r"(b));
    return r;
}
// D = A(16x16 f16,row) @ B(16x8 f16,col) + C  (f32 accum)
__device__ __forceinline__ void mma16816h(float* d, const uint32_t* a, const uint32_t* b0,
                                          const uint32_t* b1, const float* c) {
    asm("mma.sync.aligned.m16n8k16.row.col.f32.f16.f16.f32 "
        "{%0,%1,%2,%3}, {%4,%5,%6,%7}, {%8,%9}, {%10,%11,%12,%13};"
        : "=f"(d[0]), "=f"(d[1]), "=f"(d[2]), "=f"(d[3])
        : "r"(a[0]), "r"(a[1]), "r"(a[2]), "r"(a[3]),
          "r"(*b0), "r"(*b1),
          "f"(c[0]), "f"(c[1]), "f"(c[2]), "f"(c[3]));
}

// ---------------- kernel 1: build f16 S tiles (full-tile) ----------------------
__global__ void __launch_bounds__(256)
build_S_tiles(const float* __restrict__ vocab_emb) {
    __shared__ __half T[128][34];                // +2 pad
    const int t = threadIdx.x, vt = blockIdx.x;
    const int v0 = vt * VT;

#pragma unroll
    for (int k = 0; k < 16; k++) {
        int idx = k * 256 + t;                   // 0..4095
        int v = idx >> 5, h = idx & 31;
        const float4* p = (const float4*)(vocab_emb + (size_t)(v0 + v) * N_EMBD + h * HEAD_DIM);
        float s = 0.f;
#pragma unroll
        for (int i = 0; i < 8; i++) { float4 f = p[i]; s += (f.x + f.y) + (f.z + f.w); }
        T[v][h] = __float2half_rn(s);
    }
    __syncthreads();

    char* gk = g_Skv + (size_t)vt * SKV_TILE;
#pragma unroll
    for (int k = 0; k < 8; k++) {
        int idx = k * 256 + t;                   // v=idx>>4, c=idx&15
        int v = idx >> 4, c = idx & 15;
        uint32_t val = *(const uint32_t*)&T[v][2 * c];
        *(uint32_t*)(gk + v * SKV_ROW + c * 4) = val;
    }
    char* gh = g_Shv + (size_t)vt * SHV_TILE;
#pragma unroll
    for (int k = 0; k < 8; k++) {
        int idx = k * 256 + t;                   // h=idx>>6, c=idx&63
        int h = idx >> 6, c = idx & 63;
        uint16_t a = *(const uint16_t*)&T[2 * c][h];
        uint16_t b = *(const uint16_t*)&T[2 * c + 1][h];
        uint32_t val = ((uint32_t)b << 16) | (uint32_t)a;
        *(uint32_t*)(gh + h * SHV_ROW + c * 4) = val;
    }
}

// ---------------- kernel 2: Q = FFN(x) * log2e/temp -> f16 ---------------------
__global__ void __launch_bounds__(256)
qbuild_kernel(const float* __restrict__ x,
              const float* __restrict__ W, const float* __restrict__ b,
              const float* __restrict__ temps) {
    __shared__ float sW[32 * 33];
    __shared__ float sx[8][32];
    const int t = threadIdx.x;
    const int row0 = blockIdx.x * 8;
#pragma unroll
    for (int k = 0; k < 4; k++) {
        int i = k * 256 + t;
        sW[(i >> 5) * 33 + (i & 31)] = W[i];
    }
    const int rl = t >> 5, d = t & 31;
    const int row = row0 + rl;
    sx[rl][d] = x[(size_t)row * 32 + d];
    __syncthreads();

    float s = b[d];
    const float* wr = sW + d * 33;
#pragma unroll
    for (int h = 0; h < 32; h++) s = fmaf(sx[rl][h], wr[h], s);
    float s2 = LOG2E / fmaxf(temps[row & 31], TEMP_MIN);
    g_Qh[row * 32 + d] = __float2half_rn(s * s2);
}

// ---------------- flash kernel: 4 warps, M=32/warp, occ 5 ----------------------
// grid = MTILES*NSPLIT.  blockDim = 128 (4 warps).
__global__ void __launch_bounds__(128, 5)
flash_kernel() {
    __shared__ __align__(16) char skv[2][SKV_TILE];
    __shared__ __align__(16) char shv[2][SHV_TILE];

    const int tid = threadIdx.x, w = tid >> 5, lane = tid & 31;
    const int gid = lane >> 2, tig = lane & 3;
    const int lane7 = lane & 7, laneg = lane >> 3;
    const int m = blockIdx.x & (MTILES - 1), s = blockIdx.x >> 5;
    const int rw0 = m * 128 + w * 32;
    const int t0 = (s * NTILES) / NSPLIT, t1 = ((s + 1) * NTILES) / NSPLIT;
    const int nT = t1 - t0;

    const uint32_t skv_b[2] = { smem_to_u32(skv[0]), smem_to_u32(skv[1]) };
    const uint32_t shv_b[2] = { smem_to_u32(shv[0]), smem_to_u32(shv[1]) };

    // ldmatrix per-lane offsets
    const uint32_t aA_off = (uint32_t)(lane7 * SKV_ROW + laneg * 16);
    const uint32_t bB_off = (uint32_t)((((laneg >> 1) * 8) + lane7) * SHV_ROW + (laneg & 1) * 16);

    // ---- persistent Q fragments ----
    uint32_t qf[2][2][4];
#pragma unroll
    for (int f = 0; f < 2; f++)
#pragma unroll
    for (int ks = 0; ks < 2; ks++) {
        int c0 = ks * 16 + 2 * tig;
        int rb = rw0 + 16 * f;
        qf[f][ks][0] = *(const uint32_t*)&g_Qh[(size_t)(rb + gid)     * 32 + c0];
        qf[f][ks][1] = *(const uint32_t*)&g_Qh[(size_t)(rb + gid + 8) * 32 + c0];
        qf[f][ks][2] = *(const uint32_t*)&g_Qh[(size_t)(rb + gid)     * 32 + c0 + 8];
        qf[f][ks][3] = *(const uint32_t*)&g_Qh[(size_t)(rb + gid + 8) * 32 + c0 + 8];
    }

    float outacc[2][4][4];
#pragma unroll
    for (int f = 0; f < 2; f++)
#pragma unroll
    for (int n2 = 0; n2 < 4; n2++)
#pragma unroll
        for (int k = 0; k < 4; k++) outacc[f][n2][k] = 0.f;
    float zf[2][2] = {{0.f, 0.f}, {0.f, 0.f}};   // [f][rowgroup] f32 Z accumulators

    // ---- cp.async tile copy (128 threads): SKV 640 chunks, SHV 544 chunks ----
    auto issue_tile = [&](int stg, int vt) {
        const char* gk = g_Skv + (size_t)vt * SKV_TILE;
        const char* gh = g_Shv + (size_t)vt * SHV_TILE;
        uint32_t dk = skv_b[stg], dh = shv_b[stg];
#pragma unroll
        for (int c = 0; c < 5; c++)
            CP_ASYNC16(dk + c * 2048 + tid * 16, gk + c * 2048 + tid * 16);
#pragma unroll
        for (int c = 0; c < 4; c++)
            CP_ASYNC16(dh + c * 2048 + tid * 16, gh + c * 2048 + tid * 16);
        if (tid < 32) CP_ASYNC16(dh + 8192 + tid * 16, gh + 8192 + tid * 16);
        CP_COMMIT();
    };

    issue_tile(0, t0);

    for (int i = 0; i < nT; i++) {
        const int stg = i & 1;
        __syncthreads();
        if (i + 1 < nT) issue_tile((i + 1) & 1, t0 + i + 1);
        if (i + 1 < nT) { CP_WAIT(1); } else { CP_WAIT(0); }
        __syncthreads();

        const uint32_t kv = skv_b[stg] + aA_off;
        const uint32_t hvB = shv_b[stg] + bB_off;

        // per-tile f16x2 Z accumulators (16 adds max, values ~O(10) -> safe)
        uint32_t zt[2][2] = {{0u, 0u}, {0u, 0u}};

#pragma unroll 2
        for (int c0 = 0; c0 < VT; c0 += 16) {  // 16-vocab chunk
            uint32_t bA0[4], bA1[4], bb[8];
            LDSM4(bA0[0], bA0[1], bA0[2], bA0[3], kv + (uint32_t)(c0 * SKV_ROW));
            LDSM4(bA1[0], bA1[1], bA1[2], bA1[3], kv + (uint32_t)((c0 + 8) * SKV_ROW));
            LDSM4(bb[0], bb[1], bb[2], bb[3], hvB + (uint32_t)(c0 * 2));
            LDSM4(bb[4], bb[5], bb[6], bb[7], hvB + (uint32_t)(c0 * 2) + 4352u);

            uint32_t pa[2][4];
#pragma unroll
            for (int f = 0; f < 2; f++) {
                float d0[4] = {0.f, 0.f, 0.f, 0.f}, d1[4] = {0.f, 0.f, 0.f, 0.f};
                mma16816h(d0, qf[f][0], &bA0[0], &bA0[1], d0);
                mma16816h(d0, qf[f][1], &bA0[2], &bA0[3], d0);
                mma16816h(d1, qf[f][0], &bA1[0], &bA1[1], d1);
                mma16816h(d1, qf[f][1], &bA1[2], &bA1[3], d1);
                pa[f][0] = ex2_f16x2(cvt_f16x2(d0[0], d0[1]));
                pa[f][1] = ex2_f16x2(cvt_f16x2(d0[2], d0[3]));
                pa[f][2] = ex2_f16x2(cvt_f16x2(d1[0], d1[1]));
                pa[f][3] = ex2_f16x2(cvt_f16x2(d1[2], d1[3]));
                zt[f][0] = hadd2u(zt[f][0], hadd2u(pa[f][0], pa[f][2]));
                zt[f][1] = hadd2u(zt[f][1], hadd2u(pa[f][1], pa[f][3]));
            }

#pragma unroll
            for (int n2 = 0; n2 < 4; n2++) {
                mma16816h(outacc[0][n2], pa[0], &bb[2 * n2], &bb[2 * n2 + 1], outacc[0][n2]);
                mma16816h(outacc[1][n2], pa[1], &bb[2 * n2], &bb[2 * n2 + 1], outacc[1][n2]);
            }
        }

        // fold tile Z into f32
#pragma unroll
        for (int f = 0; f < 2; f++)
#pragma unroll
        for (int r = 0; r < 2; r++) {
            float2 v = __half22float2(*(__half2*)&zt[f][r]);
            zf[f][r] += v.x + v.y;
        }
    }

    // ---- epilogue: reduce Z over the 4 tig lanes, write f16x2 partials ----
#pragma unroll
    for (int f = 0; f < 2; f++)
#pragma unroll
    for (int r = 0; r < 2; r++) {
        zf[f][r] += __shfl_xor_sync(0xFFFFFFFFu, zf[f][r], 1);
        zf[f][r] += __shfl_xor_sync(0xFFFFFFFFu, zf[f][r], 2);
    }

#pragma unroll
    for (int f = 0; f < 2; f++) {
        const int r0g = rw0 + 16 * f + gid, r1g = r0g + 8;
        if (tig == 0) {
            g_Zpart[s * NROWS + r0g] = zf[f][0];
            g_Zpart[s * NROWS + r1g] = zf[f][1];
        }
#pragma unroll
        for (int n2 = 0; n2 < 4; n2++) {
            // cols n2*8+2*tig (+1): one packed u32 per row, u32 index n2*4+tig
            g_OpartH[((size_t)s * NROWS + r0g) * 16 + n2 * 4 + tig] =
                cvt_f16x2(outacc[f][n2][0], outacc[f][n2][1]);
            g_OpartH[((size_t)s * NROWS + r1g) * 16 + n2 * 4 + tig] =
                cvt_f16x2(outacc[f][n2][2], outacc[f][n2][3]);
        }
    }
}

// ---------------- merge partials + gate -> Q2 (pre-scaled) ---------------------
__global__ void __launch_bounds__(256)
merge_gate_kernel(const float* __restrict__ x,
                  const float* __restrict__ W_ref, const float* __restrict__ b_ref,
                  const float* __restrict__ W_gate, const float* __restrict__ b_gate,
                  const float* __restrict__ temps) {
    __shared__ float sWr[32 * 33], sWg[32 * 33];
    __shared__ float sx[8][32];
    const int t = threadIdx.x;
    const int row0 = blockIdx.x * 8;
#pragma unroll
    for (int k = 0; k < 4; k++) {
        int i = k * 256 + t;
        int di = (i >> 5) * 33 + (i & 31);
        sWr[di] = W_ref[i];
        sWg[di] = W_gate[i];
    }
    const int rl = t >> 5, d = t & 31;
    const int row = row0 + rl;
    sx[rl][d] = x[(size_t)row * 32 + d];

    float O = 0.f, Z = 0.f;
#pragma unroll
    for (int s = 0; s < NSPLIT; s++) {
        uint32_t u = g_OpartH[((size_t)s * NROWS + row) * 16 + (d >> 1)];
        float2 v = __half22float2(*(__half2*)&u);
        O += (d & 1) ? v.y : v.x;
        Z += g_Zpart[s * NROWS + row];
    }
    float vout = O / Z;
    __syncthreads();

    float sr = b_ref[d], sg = b_gate[d];
    const float* wr = sWr + d * 33;
    const float* wg = sWg + d * 33;
#pragma unroll
    for (int h = 0; h < 32; h++) {
        float xv = sx[rl][h];
        sr = fmaf(xv, wr[h], sr);
        sg = fmaf(xv, wg[h], sg);
    }
    float refv = tanhf(sr);
    float g = 1.0f / (1.0f + __expf(-sg));
    float q2 = vout * (1.0f - g) + refv * g;
    float s2 = LOG2E / fmaxf(temps[row & 31], TEMP_MIN);
    g_Qh[row * 32 + d] = __float2half_rn(q2 * s2);
}

// ---------------- final merge -> out (vectorized) ------------------------------
__global__ void final_kernel(float* __restrict__ out) {
    int gid = blockIdx.x * blockDim.x + threadIdx.x;      // NROWS*8
    if (gid >= NROWS * 8) return;
    int row = gid >> 3, c4 = (gid & 7) * 4;               // 4 output cols per thread
    float4 O = make_float4(0.f, 0.f, 0.f, 0.f);
    float Z = 0.f;
#pragma unroll
    for (int s = 0; s < NSPLIT; s++) {
        const uint32_t* p = &g_OpartH[((size_t)s * NROWS + row) * 16 + (c4 >> 1)];
        uint2 u = *(const uint2*)p;
        float2 a = __half22float2(*(__half2*)&u.x);
        float2 b = __half22float2(*(__half2*)&u.y);
        O.x += a.x; O.y += a.y; O.z += b.x; O.w += b.y;
        Z += g_Zpart[s * NROWS + row];
    }
    float iz = 1.0f / Z;
    *(float4*)&out[(size_t)row * 32 + c4] =
        make_float4(O.x * iz, O.y * iz, O.z * iz, O.w * iz);
}

// ---------------- launch -------------------------------------------------------
extern "C" void kernel_launch(void* const* d_in, const int* in_sizes, int n_in,
                              void* d_out, int out_size) {
    const float* x         = (const float*)d_in[0];
    const float* vocab_emb = (const float*)d_in[1];
    const float* W_ffn     = (const float*)d_in[2];
    const float* b_ffn     = (const float*)d_in[3];
    const float* temps     = (const float*)d_in[4];
    const float* W_ref     = (const float*)d_in[5];
    const float* b_ref     = (const float*)d_in[6];
    const float* W_gate    = (const float*)d_in[7];
    const float* b_gate    = (const float*)d_in[8];
    float* out = (float*)d_out;

    build_S_tiles<<<NTILES, 256>>>(vocab_emb);
    qbuild_kernel<<<NROWS / 8, 256>>>(x, W_ffn, b_ffn, temps);
    flash_kernel<<<MTILES * NSPLIT, 128>>>();
    merge_gate_kernel<<<NROWS / 8, 256>>>(x, W_ref, b_ref, W_gate, b_gate, temps);
    flash_kernel<<<MTILES * NSPLIT, 128>>>();
    final_kernel<<<(NROWS * 8 + 255) / 256, 256>>>(out);
}

// round 15
// speedup vs baseline: 1.1989x; 1.0335x over previous
#include <cuda_runtime.h>
#include <cuda_fp16.h>
#include <cstdint>

#define N_HEAD   32
#define HEAD_DIM 32
#define N_EMBD   1024
#define VOCAB    32000
#define NTOK     128
#define NROWS    4096            // NTOK * N_HEAD
#define TEMP_MIN 0.1f
#define LOG2E    1.4426950408889634f

#define VT       128             // vocab columns per tile
#define NTILES   250             // 32000 / 128
#define NSPLIT   18
#define MTILES   32              // 4096 / 128

// single padded tile layout (LDSM-conflict-free stride); serves BOTH GEMMs:
//   non-trans ldmatrix -> GEMM1 B-fragments, trans ldmatrix -> GEMM2 B-fragments
#define SKV_ROW   80             // 32 f16 (64B) + 16B pad
#define SKV_TILE  (VT * SKV_ROW)          // 10240 B

// ---------------- global scratch ----------------------------------------------
__device__ __align__(256) char g_Skv[NTILES * SKV_TILE];   // [tile][v][ch] f16 padded
__device__ __align__(256) __half g_Qh[NROWS * 32];         // pre-scaled by log2e/temp
__device__ __align__(256) uint32_t g_OpartH[NSPLIT * NROWS * 16];  // f16x2-packed partials
__device__ __align__(256) float g_Zpart[NSPLIT * NROWS];

// ---------------- helpers ------------------------------------------------------
__device__ __forceinline__ uint32_t smem_to_u32(const void* p) {
    uint32_t a;
    asm("{ .reg .u64 t; cvta.to.shared.u64 t, %1; cvt.u32.u64 %0, t; }" : "=r"(a) : "l"(p));
    return a;
}
#define CP_ASYNC16(dst_u32, src_ptr) \
    asm volatile("cp.async.cg.shared.global [%0], [%1], 16;" \
                 :: "r"(dst_u32), "l"(src_ptr) : "memory")
#define CP_COMMIT()  asm volatile("cp.async.commit_group;" ::: "memory")
#define CP_WAIT(n)   asm volatile("cp.async.wait_group %0;" :: "n"(n) : "memory")

#define LDSM4(r0, r1, r2, r3, addr) \
    asm volatile("ldmatrix.sync.aligned.m8n8.x4.shared.b16 {%0,%1,%2,%3}, [%4];" \
                 : "=r"(r0), "=r"(r1), "=r"(r2), "=r"(r3) : "r"(addr))
#define LDSM4T(r0, r1, r2, r3, addr) \
    asm volatile("ldmatrix.sync.aligned.m8n8.x4.trans.shared.b16 {%0,%1,%2,%3}, [%4];" \
                 : "=r"(r0), "=r"(r1), "=r"(r2), "=r"(r3) : "r"(addr))

// pack two f32 into f16x2 (first arg -> LOW half), then exp2 both
__device__ __forceinline__ uint32_t cvt_f16x2(float lo, float hi) {
    uint32_t r;
    asm("cvt.rn.f16x2.f32 %0, %1, %2;" : "=r"(r) : "f"(hi), "f"(lo));
    return r;
}
__device__ __forceinline__ uint32_t ex2_f16x2(uint32_t x) {
    uint32_t r;
    asm("ex2.approx.f16x2 %0, %1;" : "=r"(r) : "r"(x));
    return r;
}
__device__ __forceinline__ uint32_t hadd2u(uint32_t a, uint32_t b) {
    uint32_t r;
    asm("add.f16x2 %0, %1, %2;" : "=r"(r) : "r"(a), "r"(b));
    return r;
}
// D = A(16x16 f16,row) @ B(16x8 f16,col) + C  (f32 accum)
__device__ __forceinline__ void mma16816h(float* d, const uint32_t* a, const uint32_t* b0,
                                          const uint32_t* b1, const float* c) {
    asm("mma.sync.aligned.m16n8k16.row.col.f32.f16.f16.f32 "
        "{%0,%1,%2,%3}, {%4,%5,%6,%7}, {%8,%9}, {%10,%11,%12,%13};"
        : "=f"(d[0]), "=f"(d[1]), "=f"(d[2]), "=f"(d[3])
        : "r"(a[0]), "r"(a[1]), "r"(a[2]), "r"(a[3]),
          "r"(*b0), "r"(*b1),
          "f"(c[0]), "f"(c[1]), "f"(c[2]), "f"(c[3]));
}

// ---------------- kernel 1: build f16 S tiles (Skv only) -----------------------
__global__ void __launch_bounds__(256)
build_S_tiles(const float* __restrict__ vocab_emb) {
    __shared__ __half T[128][34];                // +2 pad
    const int t = threadIdx.x, vt = blockIdx.x;
    const int v0 = vt * VT;

#pragma unroll
    for (int k = 0; k < 16; k++) {
        int idx = k * 256 + t;                   // 0..4095
        int v = idx >> 5, h = idx & 31;
        const float4* p = (const float4*)(vocab_emb + (size_t)(v0 + v) * N_EMBD + h * HEAD_DIM);
        float s = 0.f;
#pragma unroll
        for (int i = 0; i < 8; i++) { float4 f = p[i]; s += (f.x + f.y) + (f.z + f.w); }
        T[v][h] = __float2half_rn(s);
    }
    __syncthreads();

    char* gk = g_Skv + (size_t)vt * SKV_TILE;
#pragma unroll
    for (int k = 0; k < 8; k++) {
        int idx = k * 256 + t;                   // v=idx>>4, c=idx&15
        int v = idx >> 4, c = idx & 15;
        uint32_t val = *(const uint32_t*)&T[v][2 * c];
        *(uint32_t*)(gk + v * SKV_ROW + c * 4) = val;
    }
}

// ---------------- kernel 2: Q = FFN(x) * log2e/temp -> f16 ---------------------
__global__ void __launch_bounds__(256)
qbuild_kernel(const float* __restrict__ x,
              const float* __restrict__ W, const float* __restrict__ b,
              const float* __restrict__ temps) {
    __shared__ float sW[32 * 33];
    __shared__ float sx[8][32];
    const int t = threadIdx.x;
    const int row0 = blockIdx.x * 8;
#pragma unroll
    for (int k = 0; k < 4; k++) {
        int i = k * 256 + t;
        sW[(i >> 5) * 33 + (i & 31)] = W[i];
    }
    const int rl = t >> 5, d = t & 31;
    const int row = row0 + rl;
    sx[rl][d] = x[(size_t)row * 32 + d];
    __syncthreads();

    float s = b[d];
    const float* wr = sW + d * 33;
#pragma unroll
    for (int h = 0; h < 32; h++) s = fmaf(sx[rl][h], wr[h], s);
    float s2 = LOG2E / fmaxf(temps[row & 31], TEMP_MIN);
    g_Qh[row * 32 + d] = __float2half_rn(s * s2);
}

// ---------------- flash kernel: single-tile, trans-LDSM GEMM2 B ---------------
// grid = MTILES*NSPLIT.  blockDim = 128 (4 warps).
__global__ void __launch_bounds__(128, 4)
flash_kernel() {
    __shared__ __align__(16) char skv[2][SKV_TILE];

    const int tid = threadIdx.x, w = tid >> 5, lane = tid & 31;
    const int gid = lane >> 2, tig = lane & 3;
    const int lane7 = lane & 7, laneg = lane >> 3;
    const int m = blockIdx.x & (MTILES - 1), s = blockIdx.x >> 5;
    const int rw0 = m * 128 + w * 32;
    const int t0 = (s * NTILES) / NSPLIT, t1 = ((s + 1) * NTILES) / NSPLIT;
    const int nT = t1 - t0;

    const uint32_t skv_b[2] = { smem_to_u32(skv[0]), smem_to_u32(skv[1]) };

    // non-trans (GEMM1 B): rows v=c0(+8j)+lane7, 16B col-block laneg
    const uint32_t aA_off = (uint32_t)(lane7 * SKV_ROW + laneg * 16);
    // trans (GEMM2 B): tile t=laneg: khalf=t&1 (v rows +8), n2=t>>1 (ch block 16B)
    const uint32_t bT_off = (uint32_t)((lane7 + (laneg & 1) * 8) * SKV_ROW + (laneg >> 1) * 16);

    // ---- persistent Q fragments ----
    uint32_t qf[2][2][4];
#pragma unroll
    for (int f = 0; f < 2; f++)
#pragma unroll
    for (int ks = 0; ks < 2; ks++) {
        int c0 = ks * 16 + 2 * tig;
        int rb = rw0 + 16 * f;
        qf[f][ks][0] = *(const uint32_t*)&g_Qh[(size_t)(rb + gid)     * 32 + c0];
        qf[f][ks][1] = *(const uint32_t*)&g_Qh[(size_t)(rb + gid + 8) * 32 + c0];
        qf[f][ks][2] = *(const uint32_t*)&g_Qh[(size_t)(rb + gid)     * 32 + c0 + 8];
        qf[f][ks][3] = *(const uint32_t*)&g_Qh[(size_t)(rb + gid + 8) * 32 + c0 + 8];
    }

    float outacc[2][4][4];
#pragma unroll
    for (int f = 0; f < 2; f++)
#pragma unroll
    for (int n2 = 0; n2 < 4; n2++)
#pragma unroll
        for (int k = 0; k < 4; k++) outacc[f][n2][k] = 0.f;
    float zf[2][2] = {{0.f, 0.f}, {0.f, 0.f}};   // [f][rowgroup] f32 Z accumulators

    // ---- cp.async tile copy: 640 x 16B chunks = 128 threads x 5 ----
    auto issue_tile = [&](int stg, int vt) {
        const char* gk = g_Skv + (size_t)vt * SKV_TILE;
        uint32_t dk = skv_b[stg];
#pragma unroll
        for (int c = 0; c < 5; c++)
            CP_ASYNC16(dk + c * 2048 + tid * 16, gk + c * 2048 + tid * 16);
        CP_COMMIT();
    };

    issue_tile(0, t0);

    for (int i = 0; i < nT; i++) {
        const int stg = i & 1;
        __syncthreads();
        if (i + 1 < nT) issue_tile((i + 1) & 1, t0 + i + 1);
        if (i + 1 < nT) { CP_WAIT(1); } else { CP_WAIT(0); }
        __syncthreads();

        const uint32_t kv  = skv_b[stg] + aA_off;
        const uint32_t kvT = skv_b[stg] + bT_off;

        // per-tile f16x2 Z accumulators (16 adds max, values ~O(10) -> safe)
        uint32_t zt[2][2] = {{0u, 0u}, {0u, 0u}};

#pragma unroll 2
        for (int c0 = 0; c0 < VT; c0 += 16) {  // 16-vocab chunk
            uint32_t bA0[4], bA1[4], bb[8];
            LDSM4(bA0[0], bA0[1], bA0[2], bA0[3], kv + (uint32_t)(c0 * SKV_ROW));
            LDSM4(bA1[0], bA1[1], bA1[2], bA1[3], kv + (uint32_t)((c0 + 8) * SKV_ROW));
            // GEMM2 B via trans-ldmatrix of the SAME tile: tiles (n2,khalf)
            LDSM4T(bb[0], bb[1], bb[2], bb[3], kvT + (uint32_t)(c0 * SKV_ROW));        // n2 0,1
            LDSM4T(bb[4], bb[5], bb[6], bb[7], kvT + (uint32_t)(c0 * SKV_ROW) + 32u);  // n2 2,3

            uint32_t pa[2][4];
#pragma unroll
            for (int f = 0; f < 2; f++) {
                float d0[4] = {0.f, 0.f, 0.f, 0.f}, d1[4] = {0.f, 0.f, 0.f, 0.f};
                mma16816h(d0, qf[f][0], &bA0[0], &bA0[1], d0);
                mma16816h(d0, qf[f][1], &bA0[2], &bA0[3], d0);
                mma16816h(d1, qf[f][0], &bA1[0], &bA1[1], d1);
                mma16816h(d1, qf[f][1], &bA1[2], &bA1[3], d1);
                pa[f][0] = ex2_f16x2(cvt_f16x2(d0[0], d0[1]));
                pa[f][1] = ex2_f16x2(cvt_f16x2(d0[2], d0[3]));
                pa[f][2] = ex2_f16x2(cvt_f16x2(d1[0], d1[1]));
                pa[f][3] = ex2_f16x2(cvt_f16x2(d1[2], d1[3]));
                zt[f][0] = hadd2u(zt[f][0], hadd2u(pa[f][0], pa[f][2]));
                zt[f][1] = hadd2u(zt[f][1], hadd2u(pa[f][1], pa[f][3]));
            }

#pragma unroll
            for (int n2 = 0; n2 < 4; n2++) {
                mma16816h(outacc[0][n2], pa[0], &bb[2 * n2], &bb[2 * n2 + 1], outacc[0][n2]);
                mma16816h(outacc[1][n2], pa[1], &bb[2 * n2], &bb[2 * n2 + 1], outacc[1][n2]);
            }
        }

        // fold tile Z into f32
#pragma unroll
        for (int f = 0; f < 2; f++)
#pragma unroll
        for (int r = 0; r < 2; r++) {
            float2 v = __half22float2(*(__half2*)&zt[f][r]);
            zf[f][r] += v.x + v.y;
        }
    }

    // ---- epilogue: reduce Z over the 4 tig lanes, write f16x2 partials ----
#pragma unroll
    for (int f = 0; f < 2; f++)
#pragma unroll
    for (int r = 0; r < 2; r++) {
        zf[f][r] += __shfl_xor_sync(0xFFFFFFFFu, zf[f][r], 1);
        zf[f][r] += __shfl_xor_sync(0xFFFFFFFFu, zf[f][r], 2);
    }

#pragma unroll
    for (int f = 0; f < 2; f++) {
        const int r0g = rw0 + 16 * f + gid, r1g = r0g + 8;
        if (tig == 0) {
            g_Zpart[s * NROWS + r0g] = zf[f][0];
            g_Zpart[s * NROWS + r1g] = zf[f][1];
        }
#pragma unroll
        for (int n2 = 0; n2 < 4; n2++) {
            // cols n2*8+2*tig (+1): one packed u32 per row, u32 index n2*4+tig
            g_OpartH[((size_t)s * NROWS + r0g) * 16 + n2 * 4 + tig] =
                cvt_f16x2(outacc[f][n2][0], outacc[f][n2][1]);
            g_OpartH[((size_t)s * NROWS + r1g) * 16 + n2 * 4 + tig] =
                cvt_f16x2(outacc[f][n2][2], outacc[f][n2][3]);
        }
    }
}

// ---------------- merge partials + gate -> Q2 (pre-scaled) ---------------------
__global__ void __launch_bounds__(256)
merge_gate_kernel(const float* __restrict__ x,
                  const float* __restrict__ W_ref, const float* __restrict__ b_ref,
                  const float* __restrict__ W_gate, const float* __restrict__ b_gate,
                  const float* __restrict__ temps) {
    __shared__ float sWr[32 * 33], sWg[32 * 33];
    __shared__ float sx[8][32];
    const int t = threadIdx.x;
    const int row0 = blockIdx.x * 8;
#pragma unroll
    for (int k = 0; k < 4; k++) {
        int i = k * 256 + t;
        int di = (i >> 5) * 33 + (i & 31);
        sWr[di] = W_ref[i];
        sWg[di] = W_gate[i];
    }
    const int rl = t >> 5, d = t & 31;
    const int row = row0 + rl;
    sx[rl][d] = x[(size_t)row * 32 + d];

    float O = 0.f, Z = 0.f;
#pragma unroll
    for (int s = 0; s < NSPLIT; s++) {
        uint32_t u = g_OpartH[((size_t)s * NROWS + row) * 16 + (d >> 1)];
        float2 v = __half22float2(*(__half2*)&u);
        O += (d & 1) ? v.y : v.x;
        Z += g_Zpart[s * NROWS + row];
    }
    float vout = O / Z;
    __syncthreads();

    float sr = b_ref[d], sg = b_gate[d];
    const float* wr = sWr + d * 33;
    const float* wg = sWg + d * 33;
#pragma unroll
    for (int h = 0; h < 32; h++) {
        float xv = sx[rl][h];
        sr = fmaf(xv, wr[h], sr);
        sg = fmaf(xv, wg[h], sg);
    }
    float refv = tanhf(sr);
    float g = 1.0f / (1.0f + __expf(-sg));
    float q2 = vout * (1.0f - g) + refv * g;
    float s2 = LOG2E / fmaxf(temps[row & 31], TEMP_MIN);
    g_Qh[row * 32 + d] = __float2half_rn(q2 * s2);
}

// ---------------- final merge -> out (vectorized) ------------------------------
__global__ void final_kernel(float* __restrict__ out) {
    int gid = blockIdx.x * blockDim.x + threadIdx.x;      // NROWS*8
    if (gid >= NROWS * 8) return;
    int row = gid >> 3, c4 = (gid & 7) * 4;               // 4 output cols per thread
    float4 O = make_float4(0.f, 0.f, 0.f, 0.f);
    float Z = 0.f;
#pragma unroll
    for (int s = 0; s < NSPLIT; s++) {
        const uint32_t* p = &g_OpartH[((size_t)s * NROWS + row) * 16 + (c4 >> 1)];
        uint2 u = *(const uint2*)p;
        float2 a = __half22float2(*(__half2*)&u.x);
        float2 b = __half22float2(*(__half2*)&u.y);
        O.x += a.x; O.y += a.y; O.z += b.x; O.w += b.y;
        Z += g_Zpart[s * NROWS + row];
    }
    float iz = 1.0f / Z;
    *(float4*)&out[(size_t)row * 32 + c4] =
        make_float4(O.x * iz, O.y * iz, O.z * iz, O.w * iz);
}

// ---------------- launch -------------------------------------------------------
extern "C" void kernel_launch(void* const* d_in, const int* in_sizes, int n_in,
                              void* d_out, int out_size) {
    const float* x         = (const float*)d_in[0];
    const float* vocab_emb = (const float*)d_in[1];
    const float* W_ffn     = (const float*)d_in[2];
    const float* b_ffn     = (const float*)d_in[3];
    const float* temps     = (const float*)d_in[4];
    const float* W_ref     = (const float*)d_in[5];
    const float* b_ref     = (const float*)d_in[6];
    const float* W_gate    = (const float*)d_in[7];
    const float* b_gate    = (const float*)d_in[8];
    float* out = (float*)d_out;

    build_S_tiles<<<NTILES, 256>>>(vocab_emb);
    qbuild_kernel<<<NROWS / 8, 256>>>(x, W_ffn, b_ffn, temps);
    flash_kernel<<<MTILES * NSPLIT, 128>>>();
    merge_gate_kernel<<<NROWS / 8, 256>>>(x, W_ref, b_ref, W_gate, b_gate, temps);
    flash_kernel<<<MTILES * NSPLIT, 128>>>();
    final_kernel<<<(NROWS * 8 + 255) / 256, 256>>>(out);
}

// round 16
// speedup vs baseline: 1.1992x; 1.0002x over previous
#include <cuda_runtime.h>
#include <cuda_fp16.h>
#include <cstdint>

#define N_HEAD   32
#define HEAD_DIM 32
#define N_EMBD   1024
#define VOCAB    32000
#define NTOK     128
#define NROWS    4096            // NTOK * N_HEAD
#define TEMP_MIN 0.1f
#define LOG2E    1.4426950408889634f

#define VT       128             // vocab columns per tile
#define NTILES   250             // 32000 / 128
#define NSPLIT   18
#define MTILES   32              // 4096 / 128
#define NSTAGE   4

// single padded tile layout (LDSM-conflict-free stride); serves BOTH GEMMs:
//   non-trans ldmatrix -> GEMM1 B-fragments, trans ldmatrix -> GEMM2 B-fragments
#define SKV_ROW   80             // 32 f16 (64B) + 16B pad
#define SKV_TILE  (VT * SKV_ROW)          // 10240 B

// ---------------- global scratch ----------------------------------------------
__device__ __align__(256) char g_Skv[NTILES * SKV_TILE];   // [tile][v][ch] f16 padded
__device__ __align__(256) __half g_Qh[NROWS * 32];         // pre-scaled by log2e/temp
__device__ __align__(256) uint32_t g_OpartH[NSPLIT * NROWS * 16];  // f16x2-packed partials
__device__ __align__(256) float g_Zpart[NSPLIT * NROWS];

// ---------------- helpers ------------------------------------------------------
__device__ __forceinline__ uint32_t smem_to_u32(const void* p) {
    uint32_t a;
    asm("{ .reg .u64 t; cvta.to.shared.u64 t, %1; cvt.u32.u64 %0, t; }" : "=r"(a) : "l"(p));
    return a;
}
#define CP_ASYNC16(dst_u32, src_ptr) \
    asm volatile("cp.async.cg.shared.global [%0], [%1], 16;" \
                 :: "r"(dst_u32), "l"(src_ptr) : "memory")
#define CP_COMMIT()  asm volatile("cp.async.commit_group;" ::: "memory")
#define CP_WAIT(n)   asm volatile("cp.async.wait_group %0;" :: "n"(n) : "memory")

#define LDSM4(r0, r1, r2, r3, addr) \
    asm volatile("ldmatrix.sync.aligned.m8n8.x4.shared.b16 {%0,%1,%2,%3}, [%4];" \
                 : "=r"(r0), "=r"(r1), "=r"(r2), "=r"(r3) : "r"(addr))
#define LDSM4T(r0, r1, r2, r3, addr) \
    asm volatile("ldmatrix.sync.aligned.m8n8.x4.trans.shared.b16 {%0,%1,%2,%3}, [%4];" \
                 : "=r"(r0), "=r"(r1), "=r"(r2), "=r"(r3) : "r"(addr))

// pack two f32 into f16x2 (first arg -> LOW half), then exp2 both
__device__ __forceinline__ uint32_t cvt_f16x2(float lo, float hi) {
    uint32_t r;
    asm("cvt.rn.f16x2.f32 %0, %1, %2;" : "=r"(r) : "f"(hi), "f"(lo));
    return r;
}
__device__ __forceinline__ uint32_t ex2_f16x2(uint32_t x) {
    uint32_t r;
    asm("ex2.approx.f16x2 %0, %1;" : "=r"(r) : "r"(x));
    return r;
}
__device__ __forceinline__ uint32_t hadd2u(uint32_t a, uint32_t b) {
    uint32_t r;
    asm("add.f16x2 %0, %1, %2;" : "=r"(r) : "r"(a), "r"(b));
    return r;
}
// D = A(16x16 f16,row) @ B(16x8 f16,col) + C  (f32 accum)
__device__ __forceinline__ void mma16816h(float* d, const uint32_t* a, const uint32_t* b0,
                                          const uint32_t* b1, const float* c) {
    asm("mma.sync.aligned.m16n8k16.row.col.f32.f16.f16.f32 "
        "{%0,%1,%2,%3}, {%4,%5,%6,%7}, {%8,%9}, {%10,%11,%12,%13};"
        : "=f"(d[0]), "=f"(d[1]), "=f"(d[2]), "=f"(d[3])
        : "r"(a[0]), "r"(a[1]), "r"(a[2]), "r"(a[3]),
          "r"(*b0), "r"(*b1),
          "f"(c[0]), "f"(c[1]), "f"(c[2]), "f"(c[3]));
}

// ---------------- kernel 1: build f16 S tiles (Skv only) -----------------------
__global__ void __launch_bounds__(256)
build_S_tiles(const float* __restrict__ vocab_emb) {
    __shared__ __half T[128][34];                // +2 pad
    const int t = threadIdx.x, vt = blockIdx.x;
    const int v0 = vt * VT;

#pragma unroll
    for (int k = 0; k < 16; k++) {
        int idx = k * 256 + t;                   // 0..4095
        int v = idx >> 5, h = idx & 31;
        const float4* p = (const float4*)(vocab_emb + (size_t)(v0 + v) * N_EMBD + h * HEAD_DIM);
        float s = 0.f;
#pragma unroll
        for (int i = 0; i < 8; i++) { float4 f = p[i]; s += (f.x + f.y) + (f.z + f.w); }
        T[v][h] = __float2half_rn(s);
    }
    __syncthreads();

    char* gk = g_Skv + (size_t)vt * SKV_TILE;
#pragma unroll
    for (int k = 0; k < 8; k++) {
        int idx = k * 256 + t;                   // v=idx>>4, c=idx&15
        int v = idx >> 4, c = idx & 15;
        uint32_t val = *(const uint32_t*)&T[v][2 * c];
        *(uint32_t*)(gk + v * SKV_ROW + c * 4) = val;
    }
}

// ---------------- kernel 2: Q = FFN(x) * log2e/temp -> f16 ---------------------
__global__ void __launch_bounds__(256)
qbuild_kernel(const float* __restrict__ x,
              const float* __restrict__ W, const float* __restrict__ b,
              const float* __restrict__ temps) {
    __shared__ float sW[32 * 33];
    __shared__ float sx[8][32];
    const int t = threadIdx.x;
    const int row0 = blockIdx.x * 8;
#pragma unroll
    for (int k = 0; k < 4; k++) {
        int i = k * 256 + t;
        sW[(i >> 5) * 33 + (i & 31)] = W[i];
    }
    const int rl = t >> 5, d = t & 31;
    const int row = row0 + rl;
    sx[rl][d] = x[(size_t)row * 32 + d];
    __syncthreads();

    float s = b[d];
    const float* wr = sW + d * 33;
#pragma unroll
    for (int h = 0; h < 32; h++) s = fmaf(sx[rl][h], wr[h], s);
    float s2 = LOG2E / fmaxf(temps[row & 31], TEMP_MIN);
    g_Qh[row * 32 + d] = __float2half_rn(s * s2);
}

// ---------------- flash kernel: 4-stage pipeline, trans-LDSM GEMM2 B -----------
// grid = MTILES*NSPLIT.  blockDim = 128 (4 warps).
__global__ void __launch_bounds__(128, 4)
flash_kernel() {
    __shared__ __align__(16) char skv[NSTAGE][SKV_TILE];

    const int tid = threadIdx.x, w = tid >> 5, lane = tid & 31;
    const int gid = lane >> 2, tig = lane & 3;
    const int lane7 = lane & 7, laneg = lane >> 3;
    const int m = blockIdx.x & (MTILES - 1), s = blockIdx.x >> 5;
    const int rw0 = m * 128 + w * 32;
    const int t0 = (s * NTILES) / NSPLIT, t1 = ((s + 1) * NTILES) / NSPLIT;
    const int nT = t1 - t0;

    uint32_t skv_b[NSTAGE];
#pragma unroll
    for (int p = 0; p < NSTAGE; p++) skv_b[p] = smem_to_u32(skv[p]);

    // non-trans (GEMM1 B): rows v=c0(+8j)+lane7, 16B col-block laneg
    const uint32_t aA_off = (uint32_t)(lane7 * SKV_ROW + laneg * 16);
    // trans (GEMM2 B): tile t=laneg: khalf=t&1 (v rows +8), n2=t>>1 (ch block 16B)
    const uint32_t bT_off = (uint32_t)((lane7 + (laneg & 1) * 8) * SKV_ROW + (laneg >> 1) * 16);

    // ---- persistent Q fragments ----
    uint32_t qf[2][2][4];
#pragma unroll
    for (int f = 0; f < 2; f++)
#pragma unroll
    for (int ks = 0; ks < 2; ks++) {
        int c0 = ks * 16 + 2 * tig;
        int rb = rw0 + 16 * f;
        qf[f][ks][0] = *(const uint32_t*)&g_Qh[(size_t)(rb + gid)     * 32 + c0];
        qf[f][ks][1] = *(const uint32_t*)&g_Qh[(size_t)(rb + gid + 8) * 32 + c0];
        qf[f][ks][2] = *(const uint32_t*)&g_Qh[(size_t)(rb + gid)     * 32 + c0 + 8];
        qf[f][ks][3] = *(const uint32_t*)&g_Qh[(size_t)(rb + gid + 8) * 32 + c0 + 8];
    }

    float outacc[2][4][4];
#pragma unroll
    for (int f = 0; f < 2; f++)
#pragma unroll
    for (int n2 = 0; n2 < 4; n2++)
#pragma unroll
        for (int k = 0; k < 4; k++) outacc[f][n2][k] = 0.f;
    float zf[2][2] = {{0.f, 0.f}, {0.f, 0.f}};   // [f][rowgroup] f32 Z accumulators

    // ---- cp.async tile copy: 640 x 16B chunks = 128 threads x 5 ----
    auto issue_tile = [&](int stg, int vt) {
        const char* gk = g_Skv + (size_t)vt * SKV_TILE;
        uint32_t dk = skv_b[stg];
#pragma unroll
        for (int c = 0; c < 5; c++)
            CP_ASYNC16(dk + c * 2048 + tid * 16, gk + c * 2048 + tid * 16);
        CP_COMMIT();
    };

    // prologue: fill NSTAGE-1 stages (nT >= 13 always)
#pragma unroll
    for (int p = 0; p < NSTAGE - 1; p++) issue_tile(p, t0 + p);

    for (int i = 0; i < nT; i++) {
        const int stg = i & (NSTAGE - 1);
        CP_WAIT(NSTAGE - 2);                 // tile i resident
        __syncthreads();                     // all warps done with stage (i-1)&3 too
        if (i + NSTAGE - 1 < nT) issue_tile((i + NSTAGE - 1) & (NSTAGE - 1), t0 + i + NSTAGE - 1);
        else CP_COMMIT();                    // empty group keeps wait-count invariant

        const uint32_t kv  = skv_b[stg] + aA_off;
        const uint32_t kvT = skv_b[stg] + bT_off;

        // per-tile f16x2 Z accumulators (16 adds max, values ~O(10) -> safe)
        uint32_t zt[2][2] = {{0u, 0u}, {0u, 0u}};

#pragma unroll 2
        for (int c0 = 0; c0 < VT; c0 += 16) {  // 16-vocab chunk
            uint32_t bA0[4], bA1[4], bb[8];
            LDSM4(bA0[0], bA0[1], bA0[2], bA0[3], kv + (uint32_t)(c0 * SKV_ROW));
            LDSM4(bA1[0], bA1[1], bA1[2], bA1[3], kv + (uint32_t)((c0 + 8) * SKV_ROW));
            // GEMM2 B via trans-ldmatrix of the SAME tile: tiles (n2,khalf)
            LDSM4T(bb[0], bb[1], bb[2], bb[3], kvT + (uint32_t)(c0 * SKV_ROW));        // n2 0,1
            LDSM4T(bb[4], bb[5], bb[6], bb[7], kvT + (uint32_t)(c0 * SKV_ROW) + 32u);  // n2 2,3

            uint32_t pa[2][4];
#pragma unroll
            for (int f = 0; f < 2; f++) {
                float d0[4] = {0.f, 0.f, 0.f, 0.f}, d1[4] = {0.f, 0.f, 0.f, 0.f};
                mma16816h(d0, qf[f][0], &bA0[0], &bA0[1], d0);
                mma16816h(d0, qf[f][1], &bA0[2], &bA0[3], d0);
                mma16816h(d1, qf[f][0], &bA1[0], &bA1[1], d1);
                mma16816h(d1, qf[f][1], &bA1[2], &bA1[3], d1);
                pa[f][0] = ex2_f16x2(cvt_f16x2(d0[0], d0[1]));
                pa[f][1] = ex2_f16x2(cvt_f16x2(d0[2], d0[3]));
                pa[f][2] = ex2_f16x2(cvt_f16x2(d1[0], d1[1]));
                pa[f][3] = ex2_f16x2(cvt_f16x2(d1[2], d1[3]));
                zt[f][0] = hadd2u(zt[f][0], hadd2u(pa[f][0], pa[f][2]));
                zt[f][1] = hadd2u(zt[f][1], hadd2u(pa[f][1], pa[f][3]));
            }

#pragma unroll
            for (int n2 = 0; n2 < 4; n2++) {
                mma16816h(outacc[0][n2], pa[0], &bb[2 * n2], &bb[2 * n2 + 1], outacc[0][n2]);
                mma16816h(outacc[1][n2], pa[1], &bb[2 * n2], &bb[2 * n2 + 1], outacc[1][n2]);
            }
        }

        // fold tile Z into f32
#pragma unroll
        for (int f = 0; f < 2; f++)
#pragma unroll
        for (int r = 0; r < 2; r++) {
            float2 v = __half22float2(*(__half2*)&zt[f][r]);
            zf[f][r] += v.x + v.y;
        }
    }

    // ---- epilogue: reduce Z over the 4 tig lanes, write f16x2 partials ----
#pragma unroll
    for (int f = 0; f < 2; f++)
#pragma unroll
    for (int r = 0; r < 2; r++) {
        zf[f][r] += __shfl_xor_sync(0xFFFFFFFFu, zf[f][r], 1);
        zf[f][r] += __shfl_xor_sync(0xFFFFFFFFu, zf[f][r], 2);
    }

#pragma unroll
    for (int f = 0; f < 2; f++) {
        const int r0g = rw0 + 16 * f + gid, r1g = r0g + 8;
        if (tig == 0) {
            g_Zpart[s * NROWS + r0g] = zf[f][0];
            g_Zpart[s * NROWS + r1g] = zf[f][1];
        }
#pragma unroll
        for (int n2 = 0; n2 < 4; n2++) {
            // cols n2*8+2*tig (+1): one packed u32 per row, u32 index n2*4+tig
            g_OpartH[((size_t)s * NROWS + r0g) * 16 + n2 * 4 + tig] =
                cvt_f16x2(outacc[f][n2][0], outacc[f][n2][1]);
            g_OpartH[((size_t)s * NROWS + r1g) * 16 + n2 * 4 + tig] =
                cvt_f16x2(outacc[f][n2][2], outacc[f][n2][3]);
        }
    }
}

// ---------------- merge partials + gate -> Q2 (pre-scaled) ---------------------
__global__ void __launch_bounds__(256)
merge_gate_kernel(const float* __restrict__ x,
                  const float* __restrict__ W_ref, const float* __restrict__ b_ref,
                  const float* __restrict__ W_gate, const float* __restrict__ b_gate,
                  const float* __restrict__ temps) {
    __shared__ float sWr[32 * 33], sWg[32 * 33];
    __shared__ float sx[8][32];
    const int t = threadIdx.x;
    const int row0 = blockIdx.x * 8;
#pragma unroll
    for (int k = 0; k < 4; k++) {
        int i = k * 256 + t;
        int di = (i >> 5) * 33 + (i & 31);
        sWr[di] = W_ref[i];
        sWg[di] = W_gate[i];
    }
    const int rl = t >> 5, d = t & 31;
    const int row = row0 + rl;
    sx[rl][d] = x[(size_t)row * 32 + d];

    float O = 0.f, Z = 0.f;
#pragma unroll
    for (int s = 0; s < NSPLIT; s++) {
        uint32_t u = g_OpartH[((size_t)s * NROWS + row) * 16 + (d >> 1)];
        float2 v = __half22float2(*(__half2*)&u);
        O += (d & 1) ? v.y : v.x;
        Z += g_Zpart[s * NROWS + row];
    }
    float vout = O / Z;
    __syncthreads();

    float sr = b_ref[d], sg = b_gate[d];
    const float* wr = sWr + d * 33;
    const float* wg = sWg + d * 33;
#pragma unroll
    for (int h = 0; h < 32; h++) {
        float xv = sx[rl][h];
        sr = fmaf(xv, wr[h], sr);
        sg = fmaf(xv, wg[h], sg);
    }
    float refv = tanhf(sr);
    float g = 1.0f / (1.0f + __expf(-sg));
    float q2 = vout * (1.0f - g) + refv * g;
    float s2 = LOG2E / fmaxf(temps[row & 31], TEMP_MIN);
    g_Qh[row * 32 + d] = __float2half_rn(q2 * s2);
}

// ---------------- final merge -> out (vectorized) ------------------------------
__global__ void final_kernel(float* __restrict__ out) {
    int gid = blockIdx.x * blockDim.x + threadIdx.x;      // NROWS*8
    if (gid >= NROWS * 8) return;
    int row = gid >> 3, c4 = (gid & 7) * 4;               // 4 output cols per thread
    float4 O = make_float4(0.f, 0.f, 0.f, 0.f);
    float Z = 0.f;
#pragma unroll
    for (int s = 0; s < NSPLIT; s++) {
        const uint32_t* p = &g_OpartH[((size_t)s * NROWS + row) * 16 + (c4 >> 1)];
        uint2 u = *(const uint2*)p;
        float2 a = __half22float2(*(__half2*)&u.x);
        float2 b = __half22float2(*(__half2*)&u.y);
        O.x += a.x; O.y += a.y; O.z += b.x; O.w += b.y;
        Z += g_Zpart[s * NROWS + row];
    }
    float iz = 1.0f / Z;
    *(float4*)&out[(size_t)row * 32 + c4] =
        make_float4(O.x * iz, O.y * iz, O.z * iz, O.w * iz);
}

// ---------------- launch -------------------------------------------------------
extern "C" void kernel_launch(void* const* d_in, const int* in_sizes, int n_in,
                              void* d_out, int out_size) {
    const float* x         = (const float*)d_in[0];
    const float* vocab_emb = (const float*)d_in[1];
    const float* W_ffn     = (const float*)d_in[2];
    const float* b_ffn     = (const float*)d_in[3];
    const float* temps     = (const float*)d_in[4];
    const float* W_ref     = (const float*)d_in[5];
    const float* b_ref     = (const float*)d_in[6];
    const float* W_gate    = (const float*)d_in[7];
    const float* b_gate    = (const float*)d_in[8];
    float* out = (float*)d_out;

    build_S_tiles<<<NTILES, 256>>>(vocab_emb);
    qbuild_kernel<<<NROWS / 8, 256>>>(x, W_ffn, b_ffn, temps);
    flash_kernel<<<MTILES * NSPLIT, 128>>>();
    merge_gate_kernel<<<NROWS / 8, 256>>>(x, W_ref, b_ref, W_gate, b_gate, temps);
    flash_kernel<<<MTILES * NSPLIT, 128>>>();
    final_kernel<<<(NROWS * 8 + 255) / 256, 256>>>(out);
}

// round 17
// speedup vs baseline: 1.2179x; 1.0156x over previous
#include <cuda_runtime.h>
#include <cuda_fp16.h>
#include <cstdint>

#define N_HEAD   32
#define HEAD_DIM 32
#define N_EMBD   1024
#define VOCAB    32000
#define NTOK     128
#define NROWS    4096            // NTOK * N_HEAD
#define TEMP_MIN 0.1f
#define LOG2E    1.4426950408889634f

#define VT       128             // vocab columns per tile
#define NTILES   250             // 32000 / 128
#define NSPLIT   18
#define MTILES   32              // 4096 / 128
#define NSTAGE   4

// single padded tile layout (LDSM-conflict-free stride); serves BOTH GEMMs:
//   non-trans ldmatrix -> GEMM1 B-fragments, trans ldmatrix -> GEMM2 B-fragments
#define SKV_ROW   80             // 32 f16 (64B) + 16B pad
#define SKV_TILE  (VT * SKV_ROW)          // 10240 B

// ---------------- global scratch ----------------------------------------------
__device__ __align__(256) char g_Skv[NTILES * SKV_TILE];   // [tile][v][ch] f16 padded
__device__ __align__(256) __half g_Qh[NROWS * 32];         // pre-scaled by log2e/temp
__device__ __align__(256) uint32_t g_OpartH[NSPLIT * NROWS * 16];  // f16x2-packed partials
__device__ __align__(256) float g_Zpart[NSPLIT * NROWS];

// ---------------- helpers ------------------------------------------------------
__device__ __forceinline__ uint32_t smem_to_u32(const void* p) {
    uint32_t a;
    asm("{ .reg .u64 t; cvta.to.shared.u64 t, %1; cvt.u32.u64 %0, t; }" : "=r"(a) : "l"(p));
    return a;
}
#define CP_ASYNC16(dst_u32, src_ptr) \
    asm volatile("cp.async.cg.shared.global [%0], [%1], 16;" \
                 :: "r"(dst_u32), "l"(src_ptr) : "memory")
#define CP_COMMIT()  asm volatile("cp.async.commit_group;" ::: "memory")
#define CP_WAIT(n)   asm volatile("cp.async.wait_group %0;" :: "n"(n) : "memory")

#define LDSM4(r0, r1, r2, r3, addr) \
    asm volatile("ldmatrix.sync.aligned.m8n8.x4.shared.b16 {%0,%1,%2,%3}, [%4];" \
                 : "=r"(r0), "=r"(r1), "=r"(r2), "=r"(r3) : "r"(addr))
#define LDSM4T(r0, r1, r2, r3, addr) \
    asm volatile("ldmatrix.sync.aligned.m8n8.x4.trans.shared.b16 {%0,%1,%2,%3}, [%4];" \
                 : "=r"(r0), "=r"(r1), "=r"(r2), "=r"(r3) : "r"(addr))

// pack two f32 into f16x2 (first arg -> LOW half), then exp2 both
__device__ __forceinline__ uint32_t cvt_f16x2(float lo, float hi) {
    uint32_t r;
    asm("cvt.rn.f16x2.f32 %0, %1, %2;" : "=r"(r) : "f"(hi), "f"(lo));
    return r;
}
__device__ __forceinline__ uint32_t ex2_f16x2(uint32_t x) {
    uint32_t r;
    asm("ex2.approx.f16x2 %0, %1;" : "=r"(r) : "r"(x));
    return r;
}
__device__ __forceinline__ uint32_t hadd2u(uint32_t a, uint32_t b) {
    uint32_t r;
    asm("add.f16x2 %0, %1, %2;" : "=r"(r) : "r"(a), "r"(b));
    return r;
}
// D = A(16x16 f16,row) @ B(16x8 f16,col) + C  (f32 accum)
__device__ __forceinline__ void mma16816h(float* d, const uint32_t* a, const uint32_t* b0,
                                          const uint32_t* b1, const float* c) {
    asm("mma.sync.aligned.m16n8k16.row.col.f32.f16.f16.f32 "
        "{%0,%1,%2,%3}, {%4,%5,%6,%7}, {%8,%9}, {%10,%11,%12,%13};"
        : "=f"(d[0]), "=f"(d[1]), "=f"(d[2]), "=f"(d[3])
        : "r"(a[0]), "r"(a[1]), "r"(a[2]), "r"(a[3]),
          "r"(*b0), "r"(*b1),
          "f"(c[0]), "f"(c[1]), "f"(c[2]), "f"(c[3]));
}

// ---------------- kernel 1: build f16 S tiles (Skv only) -----------------------
__global__ void __launch_bounds__(256)
build_S_tiles(const float* __restrict__ vocab_emb) {
    __shared__ __half T[128][34];                // +2 pad
    const int t = threadIdx.x, vt = blockIdx.x;
    const int v0 = vt * VT;

#pragma unroll
    for (int k = 0; k < 16; k++) {
        int idx = k * 256 + t;                   // 0..4095
        int v = idx >> 5, h = idx & 31;
        const float4* p = (const float4*)(vocab_emb + (size_t)(v0 + v) * N_EMBD + h * HEAD_DIM);
        float s = 0.f;
#pragma unroll
        for (int i = 0; i < 8; i++) { float4 f = p[i]; s += (f.x + f.y) + (f.z + f.w); }
        T[v][h] = __float2half_rn(s);
    }
    __syncthreads();

    char* gk = g_Skv + (size_t)vt * SKV_TILE;
#pragma unroll
    for (int k = 0; k < 8; k++) {
        int idx = k * 256 + t;                   // v=idx>>4, c=idx&15
        int v = idx >> 4, c = idx & 15;
        uint32_t val = *(const uint32_t*)&T[v][2 * c];
        *(uint32_t*)(gk + v * SKV_ROW + c * 4) = val;
    }
}

// ---------------- kernel 2: Q = FFN(x) * log2e/temp -> f16 ---------------------
__global__ void __launch_bounds__(256)
qbuild_kernel(const float* __restrict__ x,
              const float* __restrict__ W, const float* __restrict__ b,
              const float* __restrict__ temps) {
    __shared__ float sW[32 * 33];
    __shared__ float sx[8][32];
    const int t = threadIdx.x;
    const int row0 = blockIdx.x * 8;
#pragma unroll
    for (int k = 0; k < 4; k++) {
        int i = k * 256 + t;
        sW[(i >> 5) * 33 + (i & 31)] = W[i];
    }
    const int rl = t >> 5, d = t & 31;
    const int row = row0 + rl;
    sx[rl][d] = x[(size_t)row * 32 + d];
    __syncthreads();

    float s = b[d];
    const float* wr = sW + d * 33;
#pragma unroll
    for (int h = 0; h < 32; h++) s = fmaf(sx[rl][h], wr[h], s);
    float s2 = LOG2E / fmaxf(temps[row & 31], TEMP_MIN);
    g_Qh[row * 32 + d] = __float2half_rn(s * s2);
}

// ---------------- flash kernel: 4-stage pipeline, reordered chunk body ---------
// grid = MTILES*NSPLIT.  blockDim = 128 (4 warps).
__global__ void __launch_bounds__(128, 4)
flash_kernel() {
    __shared__ __align__(16) char skv[NSTAGE][SKV_TILE];

    const int tid = threadIdx.x, w = tid >> 5, lane = tid & 31;
    const int gid = lane >> 2, tig = lane & 3;
    const int lane7 = lane & 7, laneg = lane >> 3;
    const int m = blockIdx.x & (MTILES - 1), s = blockIdx.x >> 5;
    const int rw0 = m * 128 + w * 32;
    const int t0 = (s * NTILES) / NSPLIT, t1 = ((s + 1) * NTILES) / NSPLIT;
    const int nT = t1 - t0;

    uint32_t skv_b[NSTAGE];
#pragma unroll
    for (int p = 0; p < NSTAGE; p++) skv_b[p] = smem_to_u32(skv[p]);

    // non-trans (GEMM1 B): rows v=c0(+8j)+lane7, 16B col-block laneg
    const uint32_t aA_off = (uint32_t)(lane7 * SKV_ROW + laneg * 16);
    // trans (GEMM2 B): tile t=laneg: khalf=t&1 (v rows +8), n2=t>>1 (ch block 16B)
    const uint32_t bT_off = (uint32_t)((lane7 + (laneg & 1) * 8) * SKV_ROW + (laneg >> 1) * 16);

    // ---- persistent Q fragments ----
    uint32_t qf[2][2][4];
#pragma unroll
    for (int f = 0; f < 2; f++)
#pragma unroll
    for (int ks = 0; ks < 2; ks++) {
        int c0 = ks * 16 + 2 * tig;
        int rb = rw0 + 16 * f;
        qf[f][ks][0] = *(const uint32_t*)&g_Qh[(size_t)(rb + gid)     * 32 + c0];
        qf[f][ks][1] = *(const uint32_t*)&g_Qh[(size_t)(rb + gid + 8) * 32 + c0];
        qf[f][ks][2] = *(const uint32_t*)&g_Qh[(size_t)(rb + gid)     * 32 + c0 + 8];
        qf[f][ks][3] = *(const uint32_t*)&g_Qh[(size_t)(rb + gid + 8) * 32 + c0 + 8];
    }

    float outacc[2][4][4];
#pragma unroll
    for (int f = 0; f < 2; f++)
#pragma unroll
    for (int n2 = 0; n2 < 4; n2++)
#pragma unroll
        for (int k = 0; k < 4; k++) outacc[f][n2][k] = 0.f;
    float zf[2][2] = {{0.f, 0.f}, {0.f, 0.f}};   // [f][rowgroup] f32 Z accumulators

    // ---- cp.async tile copy: 640 x 16B chunks = 128 threads x 5 ----
    auto issue_tile = [&](int stg, int vt) {
        const char* gk = g_Skv + (size_t)vt * SKV_TILE;
        uint32_t dk = skv_b[stg];
#pragma unroll
        for (int c = 0; c < 5; c++)
            CP_ASYNC16(dk + c * 2048 + tid * 16, gk + c * 2048 + tid * 16);
        CP_COMMIT();
    };

    // prologue: fill NSTAGE-1 stages (nT >= 13 always)
#pragma unroll
    for (int p = 0; p < NSTAGE - 1; p++) issue_tile(p, t0 + p);

    for (int i = 0; i < nT; i++) {
        const int stg = i & (NSTAGE - 1);
        CP_WAIT(NSTAGE - 2);                 // tile i resident
        __syncthreads();                     // all warps done with old stage
        if (i + NSTAGE - 1 < nT) issue_tile((i + NSTAGE - 1) & (NSTAGE - 1), t0 + i + NSTAGE - 1);
        else CP_COMMIT();                    // empty group keeps wait-count invariant

        const uint32_t kv  = skv_b[stg] + aA_off;
        const uint32_t kvT = skv_b[stg] + bT_off;

        // per-tile f16x2 Z accumulators (16 adds max, values ~O(10) -> safe)
        uint32_t zt[2][2] = {{0u, 0u}, {0u, 0u}};

#pragma unroll 2
        for (int c0 = 0; c0 < VT; c0 += 16) {  // 16-vocab chunk
            // GEMM1 B-fragments
            uint32_t bA0[4], bA1[4];
            LDSM4(bA0[0], bA0[1], bA0[2], bA0[3], kv + (uint32_t)(c0 * SKV_ROW));
            LDSM4(bA1[0], bA1[1], bA1[2], bA1[3], kv + (uint32_t)((c0 + 8) * SKV_ROW));

            // ALL GEMM1 MMAs first (8 tensor ops, 4 independent chains)
            float d[2][8];
#pragma unroll
            for (int f = 0; f < 2; f++) {
#pragma unroll
                for (int k = 0; k < 8; k++) d[f][k] = 0.f;
                mma16816h(&d[f][0], qf[f][0], &bA0[0], &bA0[1], &d[f][0]);
                mma16816h(&d[f][0], qf[f][1], &bA0[2], &bA0[3], &d[f][0]);
                mma16816h(&d[f][4], qf[f][0], &bA1[0], &bA1[1], &d[f][4]);
                mma16816h(&d[f][4], qf[f][1], &bA1[2], &bA1[3], &d[f][4]);
            }

            // GEMM2 B-fragments (trans-LDSM of the same tile) issued here:
            // latency hides under the exp chain below, lifetime stays short
            uint32_t bb[8];
            LDSM4T(bb[0], bb[1], bb[2], bb[3], kvT + (uint32_t)(c0 * SKV_ROW));        // n2 0,1
            LDSM4T(bb[4], bb[5], bb[6], bb[7], kvT + (uint32_t)(c0 * SKV_ROW) + 32u);  // n2 2,3

            // exp -> P fragments + Z
            uint32_t pa[2][4];
#pragma unroll
            for (int f = 0; f < 2; f++) {
                pa[f][0] = ex2_f16x2(cvt_f16x2(d[f][0], d[f][1]));
                pa[f][1] = ex2_f16x2(cvt_f16x2(d[f][2], d[f][3]));
                pa[f][2] = ex2_f16x2(cvt_f16x2(d[f][4], d[f][5]));
                pa[f][3] = ex2_f16x2(cvt_f16x2(d[f][6], d[f][7]));
                zt[f][0] = hadd2u(zt[f][0], hadd2u(pa[f][0], pa[f][2]));
                zt[f][1] = hadd2u(zt[f][1], hadd2u(pa[f][1], pa[f][3]));
            }

#pragma unroll
            for (int n2 = 0; n2 < 4; n2++) {
                mma16816h(outacc[0][n2], pa[0], &bb[2 * n2], &bb[2 * n2 + 1], outacc[0][n2]);
                mma16816h(outacc[1][n2], pa[1], &bb[2 * n2], &bb[2 * n2 + 1], outacc[1][n2]);
            }
        }

        // fold tile Z into f32
#pragma unroll
        for (int f = 0; f < 2; f++)
#pragma unroll
        for (int r = 0; r < 2; r++) {
            float2 v = __half22float2(*(__half2*)&zt[f][r]);
            zf[f][r] += v.x + v.y;
        }
    }

    // ---- epilogue: reduce Z over the 4 tig lanes, write f16x2 partials ----
#pragma unroll
    for (int f = 0; f < 2; f++)
#pragma unroll
    for (int r = 0; r < 2; r++) {
        zf[f][r] += __shfl_xor_sync(0xFFFFFFFFu, zf[f][r], 1);
        zf[f][r] += __shfl_xor_sync(0xFFFFFFFFu, zf[f][r], 2);
    }

#pragma unroll
    for (int f = 0; f < 2; f++) {
        const int r0g = rw0 + 16 * f + gid, r1g = r0g + 8;
        if (tig == 0) {
            g_Zpart[s * NROWS + r0g] = zf[f][0];
            g_Zpart[s * NROWS + r1g] = zf[f][1];
        }
#pragma unroll
        for (int n2 = 0; n2 < 4; n2++) {
            // cols n2*8+2*tig (+1): one packed u32 per row, u32 index n2*4+tig
            g_OpartH[((size_t)s * NROWS + r0g) * 16 + n2 * 4 + tig] =
                cvt_f16x2(outacc[f][n2][0], outacc[f][n2][1]);
            g_OpartH[((size_t)s * NROWS + r1g) * 16 + n2 * 4 + tig] =
                cvt_f16x2(outacc[f][n2][2], outacc[f][n2][3]);
        }
    }
}

// ---------------- merge partials + gate -> Q2 (16 rows/block, d-pair threads) --
__global__ void __launch_bounds__(256)
merge_gate_kernel(const float* __restrict__ x,
                  const float* __restrict__ W_ref, const float* __restrict__ b_ref,
                  const float* __restrict__ W_gate, const float* __restrict__ b_gate,
                  const float* __restrict__ temps) {
    __shared__ float sWr[32 * 33], sWg[32 * 33];
    __shared__ float sx[16][32];
    const int t = threadIdx.x;
    const int row0 = blockIdx.x * 16;
#pragma unroll
    for (int k = 0; k < 4; k++) {
        int i = k * 256 + t;
        int di = (i >> 5) * 33 + (i & 31);
        sWr[di] = W_ref[i];
        sWg[di] = W_gate[i];
    }
#pragma unroll
    for (int k = 0; k < 2; k++) {
        int i = k * 256 + t;                     // 0..511
        sx[i >> 5][i & 31] = x[(size_t)row0 * 32 + i];
    }

    const int rl = t >> 4;                       // local row 0..15
    const int jp = t & 15;                       // d-pair (u32) index
    const int row = row0 + rl;

    float Ox = 0.f, Oy = 0.f, Z = 0.f;
#pragma unroll
    for (int s = 0; s < NSPLIT; s++) {
        uint32_t u = g_OpartH[((size_t)s * NROWS + row) * 16 + jp];
        float2 v = __half22float2(*(__half2*)&u);
        Ox += v.x; Oy += v.y;
        Z += g_Zpart[s * NROWS + row];
    }
    float iz = 1.0f / Z;
    float vout[2] = { Ox * iz, Oy * iz };
    __syncthreads();

    const float s2t = LOG2E / fmaxf(temps[row & 31], TEMP_MIN);
    __half hq[2];
#pragma unroll
    for (int e = 0; e < 2; e++) {
        int d = 2 * jp + e;
        float sr = b_ref[d], sg = b_gate[d];
        const float* wr = sWr + d * 33;
        const float* wg = sWg + d * 33;
#pragma unroll
        for (int h = 0; h < 32; h++) {
            float xv = sx[rl][h];
            sr = fmaf(xv, wr[h], sr);
            sg = fmaf(xv, wg[h], sg);
        }
        float refv = 2.0f / (1.0f + __expf(-2.0f * sr)) - 1.0f;   // tanh
        float g = 1.0f / (1.0f + __expf(-sg));
        float q2 = vout[e] * (1.0f - g) + refv * g;
        hq[e] = __float2half_rn(q2 * s2t);
    }
    ((uint32_t*)g_Qh)[(size_t)row * 16 + jp] = *(uint32_t*)&hq[0];
}

// ---------------- final merge -> out (vectorized) ------------------------------
__global__ void final_kernel(float* __restrict__ out) {
    int gid = blockIdx.x * blockDim.x + threadIdx.x;      // NROWS*8
    if (gid >= NROWS * 8) return;
    int row = gid >> 3, c4 = (gid & 7) * 4;               // 4 output cols per thread
    float4 O = make_float4(0.f, 0.f, 0.f, 0.f);
    float Z = 0.f;
#pragma unroll
    for (int s = 0; s < NSPLIT; s++) {
        const uint32_t* p = &g_OpartH[((size_t)s * NROWS + row) * 16 + (c4 >> 1)];
        uint2 u = *(const uint2*)p;
        float2 a = __half22float2(*(__half2*)&u.x);
        float2 b = __half22float2(*(__half2*)&u.y);
        O.x += a.x; O.y += a.y; O.z += b.x; O.w += b.y;
        Z += g_Zpart[s * NROWS + row];
    }
    float iz = 1.0f / Z;
    *(float4*)&out[(size_t)row * 32 + c4] =
        make_float4(O.x * iz, O.y * iz, O.z * iz, O.w * iz);
}

// ---------------- launch -------------------------------------------------------
extern "C" void kernel_launch(void* const* d_in, const int* in_sizes, int n_in,
                              void* d_out, int out_size) {
    const float* x         = (const float*)d_in[0];
    const float* vocab_emb = (const float*)d_in[1];
    const float* W_ffn     = (const float*)d_in[2];
    const float* b_ffn     = (const float*)d_in[3];
    const float* temps     = (const float*)d_in[4];
    const float* W_ref     = (const float*)d_in[5];
    const float* b_ref     = (const float*)d_in[6];
    const float* W_gate    = (const float*)d_in[7];
    const float* b_gate    = (const float*)d_in[8];
    float* out = (float*)d_out;

    build_S_tiles<<<NTILES, 256>>>(vocab_emb);
    qbuild_kernel<<<NROWS / 8, 256>>>(x, W_ffn, b_ffn, temps);
    flash_kernel<<<MTILES * NSPLIT, 128>>>();
    merge_gate_kernel<<<NROWS / 16, 256>>>(x, W_ref, b_ref, W_gate, b_gate, temps);
    flash_kernel<<<MTILES * NSPLIT, 128>>>();
    final_kernel<<<(NROWS * 8 + 255) / 256, 256>>>(out);
}